// round 15
// baseline (speedup 1.0000x reference)
#include <cuda_runtime.h>

#define SS     256
#define BB     64
#define INF    256
#define HH     256
#define INNER  512
#define AA     64
#define LEVELS 7
#define NB     126
#define NT     512
#define NSUPER (SS + 2 * (LEVELS - 1))   // 268

#define OFF_WB1   16384
#define OFF_SG    24576
#define OFF_WA3   24768
#define OFF_B1    24832
#define OFF_BIAS1 24848
#define SMEM_FLOATS 24896
#define SMEM_BYTES  (SMEM_FLOATS * 4)

__device__ float g_xe[SS * BB * HH];
__device__ float g_dm[SS * BB];
__device__ float g_tmpL[LEVELS][BB * INNER];
__device__ float g_aL[LEVELS][BB * AA];
__device__ float r_xv[LEVELS][4][BB * HH];
__device__ float r_nm[LEVELS][4][BB];
__device__ float r_hv[LEVELS][4][BB];

// dataflow counters
__device__ unsigned cnt1[LEVELS];   // +1 per phase1-slice (18 per t)
__device__ unsigned cnt2[LEVELS];   // +1 per phase2-slice (16 per t)
__device__ unsigned cntG[LEVELS];   // +1 per t when slice-0 gates written

__device__ volatile unsigned g_arrive[NB];
__device__ volatile unsigned g_gen = 0;

__device__ __forceinline__ void gbar(unsigned ep) {
    __syncthreads();
    if (blockIdx.x == 0) {
        int tid = threadIdx.x;
        if (tid >= 1 && tid < NB) {
            while (g_arrive[tid] < ep) { }
        }
        __syncthreads();
        if (tid == 0) { __threadfence(); g_gen = ep; }
        __syncthreads();
    } else {
        if (threadIdx.x == 0) {
            __threadfence();
            g_arrive[blockIdx.x] = ep;
            while (g_gen < ep) { }
            __threadfence();
        }
        __syncthreads();
    }
}

__device__ __forceinline__ float lrelu(float z) { return z >= 0.f ? z : 0.01f * z; }

__device__ __forceinline__ void fma4(float4& a, float s, const float4& v) {
    a.x = fmaf(s, v.x, a.x); a.y = fmaf(s, v.y, a.y);
    a.z = fmaf(s, v.z, a.z); a.w = fmaf(s, v.w, a.w);
}
__device__ __forceinline__ float fcomp(const float4& v, int k) {
    return k == 0 ? v.x : k == 1 ? v.y : k == 2 ? v.z : v.w;
}
__device__ __forceinline__ void red4(float4& a, int m) {
    a.x += __shfl_xor_sync(0xffffffffu, a.x, m);
    a.y += __shfl_xor_sync(0xffffffffu, a.y, m);
    a.z += __shfl_xor_sync(0xffffffffu, a.z, m);
    a.w += __shfl_xor_sync(0xffffffffu, a.w, m);
}

// Permuted smem weight layouts (conflict-free)
__device__ __forceinline__ int permP(int k, int cc) {
    int j = k >> 5, kq = (k >> 2) & 7, kk = k & 3;
    int cg = cc >> 4, q = (cc >> 2) & 3, c = cc & 3;
    return ((((j * 4 + kk) * 2 + cg) * 32) + kq * 4 + q) * 4 + c;
}
__device__ __forceinline__ int permB(int k, int cc) {
    int j = k >> 5, kq = (k >> 2) & 7, kk = k & 3;
    int q = cc >> 2, c = cc & 3;
    return (((j * 4 + kk) * 8 + kq) * 4 + q) * 4 + c;
}

// K=256 half, 8 samples via __ldcg, permuted smem weights
template<long RS>
__device__ __forceinline__ void gemm8(const float* __restrict__ src0,
                                      const float4* __restrict__ wb4,
                                      int kq, float4 acc[8]) {
    #pragma unroll 2
    for (int j = 0; j < 8; j++) {
        const int k = j * 32 + kq * 4;
        float4 av[8];
        #pragma unroll
        for (int s = 0; s < 8; s++)
            av[s] = __ldcg((const float4*)(src0 + (long)s * RS + k));
        #pragma unroll
        for (int kk = 0; kk < 4; kk++) {
            float4 wv = wb4[(j * 4 + kk) * 64];
            #pragma unroll
            for (int s = 0; s < 8; s++) fma4(acc[s], fcomp(av[s], kk), wv);
        }
    }
}

__global__ void __launch_bounds__(NT, 1)
enc_kernel(const float* __restrict__ x, const float* __restrict__ mask,
           const float* __restrict__ W_emb, const float* __restrict__ b_emb,
           const float* __restrict__ W, const float* __restrict__ U, const float* __restrict__ b,
           const float* __restrict__ W1, const float* __restrict__ b1,
           const float* __restrict__ Wa1, const float* __restrict__ Ua1, const float* __restrict__ ba1,
           const float* __restrict__ Wa3, const float* __restrict__ ba3,
           float* __restrict__ out)
{
    extern __shared__ float smem[];
    float* const wP     = smem;
    float* const wB1    = smem + OFF_WB1;
    float* const sgb    = smem + OFF_SG;
    float* const sgx    = smem + OFF_SG + 64;
    float* const sgh    = smem + OFF_SG + 128;
    float* const swa3   = smem + OFF_WA3;
    float* const sb1    = smem + OFF_B1;
    float* const sbias1 = smem + OFF_BIAS1;

    const int tid = threadIdx.x, bid = blockIdx.x;
    const int w = tid >> 5, lane = tid & 31;
    const int kq = lane >> 2, q = lane & 3;
    unsigned ep = g_gen;

    const int lvl1 = bid / 18, cb1 = (bid % 18) * 32;
    const bool p2on = bid < 112;
    const int lvl2 = bid >> 4, cb2 = (bid & 15) * 16;
    const bool slice0 = (bid & 15) == 0;

    const int sg1 = w & 7, cg1 = w >> 3;
    const int ib1 = sg1 * 8;

    // ---- init ----
    for (int idx = bid * NT + tid; idx < SS * BB; idx += NB * NT) {
        int t = idx >> 6, i = idx & 63;
        g_dm[idx] = mask[i * SS + t];
    }
    for (int idx = bid * NT + tid; idx < LEVELS * BB * HH; idx += NB * NT)
        r_xv[idx >> 14][3][idx & 16383] = 0.f;
    for (int idx = bid * NT + tid; idx < LEVELS * BB; idx += NB * NT)
        r_hv[idx >> 6][3][idx & 63] = 0.f;
    if (bid == NB - 1 && tid < LEVELS) { cnt1[tid] = 0; cnt2[tid] = 0; cntG[tid] = 0; }

    // ---- embedding (120 blocks) ----
    if (bid < 120) {
        const int esl = bid & 7, egr = bid >> 3;
        for (int idx = tid; idx < 256 * 32; idx += NT) {
            int k = idx >> 5, cc = idx & 31;
            wP[permP(k, cc)] = W_emb[k * HH + esl * 32 + cc];
        }
        __syncthreads();
        const float4* wb4 = (const float4*)wP + cg1 * 32 + kq * 4 + q;
        for (int n = egr; n < SS; n += 15) {
            float4 acc[8];
            #pragma unroll
            for (int s = 0; s < 8; s++) acc[s] = make_float4(0.f, 0.f, 0.f, 0.f);
            gemm8<(long)SS * INF>(x + ((long)ib1 * SS + n) * INF, wb4, kq, acc);
            #pragma unroll
            for (int s = 0; s < 8; s++) { red4(acc[s], 4); red4(acc[s], 8); red4(acc[s], 16); }
            if (lane < 4) {
                int col = esl * 32 + cg1 * 16 + lane * 4;
                float4 be = __ldg((const float4*)&b_emb[col]);
                #pragma unroll
                for (int s = 0; s < 8; s++) {
                    float4 o = acc[s];
                    o.x += be.x; o.y += be.y; o.z += be.z; o.w += be.w;
                    *(float4*)&g_xe[((long)n * BB + ib1 + s) * HH + col] = o;
                }
            }
        }
        __syncthreads();
    }

    // ---- stage persistent weights ----
    for (int idx = tid; idx < 512 * 32; idx += NT) {
        int k = idx >> 5, cc = idx & 31, col = cb1 + cc;
        float v;
        if (col < 512) v = (k < 256) ? W[k * INNER + col] : U[(k - 256) * INNER + col];
        else { int a = col - 512; v = (k < 256) ? Wa1[k * AA + a] : Ua1[(k - 256) * AA + a]; }
        wP[permP(k & 255, cc) + (k >> 8) * 8192] = v;
    }
    if (p2on) {
        for (int idx = tid; idx < 512 * 16; idx += NT) {
            int k = idx >> 4, cc = idx & 15;
            wB1[permB(k, cc)] = W1[k * HH + cb2 + cc];
        }
        if (tid < 16) sb1[tid] = b1[cb2 + tid];
    }
    if (tid < 64) swa3[tid] = Wa3[tid];
    if (tid < 32) {
        int col = cb1 + tid;
        sbias1[tid] = (col < 512) ? b[col] : ba1[col - 512];
    }
    const float ba3v = __ldg(ba3);
    gbar(++ep);

    // ---- wavefront supersteps (fine-grained dataflow sync) ----
    for (int u = 0; u < NSUPER; u++) {
        // ======== phase 1 ========
        const int t1 = u - 2 * lvl1;
        if ((unsigned)t1 < SS) {
            if (lane == 0) {
                const int w1 = 16 * t1, w2 = 16 * (t1 + 1);
                for (;;) {
                    unsigned a = *(volatile unsigned*)&cnt2[lvl1];
                    unsigned bv = (lvl1 > 0) ? *(volatile unsigned*)&cnt2[lvl1 - 1] : 0u;
                    if ((int)a >= w1 && (lvl1 == 0 || (int)bv >= w2)) break;
                }
            }
            __syncwarp();

            const float* xt = (lvl1 == 0) ? &g_xe[(long)t1 * BB * HH]
                                          : r_xv[lvl1 - 1][t1 & 3];
            const float* hp = r_xv[lvl1][(t1 + 3) & 3];
            const float4* wb4 = (const float4*)wP + cg1 * 32 + kq * 4 + q;
            float4 acc[8];
            #pragma unroll
            for (int s = 0; s < 8; s++) acc[s] = make_float4(0.f, 0.f, 0.f, 0.f);
            gemm8<HH>(xt + (long)ib1 * HH, wb4,        kq, acc);
            gemm8<HH>(hp + (long)ib1 * HH, wb4 + 2048, kq, acc);
            #pragma unroll
            for (int s = 0; s < 8; s++) { red4(acc[s], 4); red4(acc[s], 8); red4(acc[s], 16); }
            if (lane < 4) {
                const int col = cb1 + cg1 * 16 + lane * 4;
                float4 bv = *(const float4*)&sbias1[cg1 * 16 + lane * 4];
                #pragma unroll
                for (int s = 0; s < 8; s++) {
                    int i = ib1 + s;
                    float4 o;
                    o.x = lrelu(acc[s].x + bv.x); o.y = lrelu(acc[s].y + bv.y);
                    o.z = lrelu(acc[s].z + bv.z); o.w = lrelu(acc[s].w + bv.w);
                    if (col < 512) *(float4*)&g_tmpL[lvl1][i * INNER + col] = o;
                    else           *(float4*)&g_aL[lvl1][i * AA + col - 512] = o;
                }
            }
            __syncthreads();
            if (tid == 0) { __threadfence(); atomicAdd(&cnt1[lvl1], 1u); }
        }

        // ======== phase 2 ========
        const int t2 = u - 2 * lvl2;
        if (p2on && (unsigned)t2 < SS) {
            // per-warp pre-gate wait
            if (lane == 0) {
                const int wTmp = 18 * (t2 + 1);
                const int wGo = t2;
                const int wGp = (t2 + 2 > 256) ? 256 : (t2 + 2);
                const int wGn = t2 - 3;
                for (;;) {
                    unsigned a  = *(volatile unsigned*)&cnt1[lvl2];
                    unsigned go = *(volatile unsigned*)&cntG[lvl2];
                    unsigned gp = (lvl2 > 0) ? *(volatile unsigned*)&cntG[lvl2 - 1] : 0u;
                    unsigned gn = (lvl2 < 6) ? *(volatile unsigned*)&cntG[lvl2 + 1] : 0u;
                    if ((int)a >= wTmp && (int)go >= wGo
                        && (lvl2 == 0 || (int)gp >= wGp)
                        && (lvl2 == 6 || (int)gn >= wGn)) break;
                }
            }
            __syncwarp();

            {   // gates (warp-local sample range i = 4w..4w+3)
                int i = tid >> 3, qtr = tid & 7;
                const float* ar = &g_aL[lvl2][i * AA + qtr * 8];
                float p = 0.f;
                #pragma unroll
                for (int c = 0; c < 8; c += 4) {
                    float4 a4 = __ldcg((const float4*)&ar[c]);
                    float4 w4 = *(const float4*)&swa3[qtr * 8 + c];
                    p += a4.x * w4.x + a4.y * w4.y + a4.z * w4.z + a4.w * w4.w;
                }
                p += __shfl_xor_sync(0xffffffffu, p, 1);
                p += __shfl_xor_sync(0xffffffffu, p, 2);
                p += __shfl_xor_sync(0xffffffffu, p, 4);
                if (qtr == 0) {
                    float sg  = 0.2f * (p + ba3v) + 0.5f;
                    float nmr = fminf(fmaxf(sg, 0.f), 1.f);
                    float lv  = (t2 == SS - 1) ? 1.f : 0.f;
                    float pm, ph;
                    if (lvl2 == 0) { pm = g_dm[t2 * BB + i]; ph = pm; }
                    else {
                        pm = (t2 == SS - 1) ? 1.f : __ldcg(&r_nm[lvl2 - 1][(t2 + 1) & 3][i]);
                        ph = __ldcg(&r_hv[lvl2 - 1][t2 & 3][i]);
                    }
                    float hvp = __ldcg(&r_hv[lvl2][(t2 + 3) & 3][i]);
                    float nm   = (1.f - lv) * (pm * ph * nmr);
                    float both = pm * ph * (1.f - nm) * hvp;
                    float xo   = pm * ph * (nm + (1.f - nm) * (1.f - hvp));
                    float ho   = (1.f - pm + pm * (1.f - ph)) * (1.f - nm) * hvp;
                    sgb[i] = both; sgx[i] = xo; sgh[i] = ho;
                    if (slice0) {
                        r_nm[lvl2][t2 & 3][i] = nm;
                        r_hv[lvl2][t2 & 3][i] = both + xo + ho;
                    }
                }
            }
            if (slice0) {
                __syncthreads();
                if (tid == 0) { __threadfence(); atomicAdd(&cntG[lvl2], 1u); }
            }
            __syncwarp();

            // B GEMM: K=512, 16 cols; warp = 4 samples x 16 cols
            const float* tl = g_tmpL[lvl2];
            const int ib = 4 * w;
            const float4* wb4 = (const float4*)wB1 + kq * 4 + q;
            float4 acc[4];
            #pragma unroll
            for (int s = 0; s < 4; s++) acc[s] = make_float4(0.f, 0.f, 0.f, 0.f);
            #pragma unroll 2
            for (int j = 0; j < 16; j++) {
                const int k = j * 32 + kq * 4;
                float4 tv[4];
                #pragma unroll
                for (int s = 0; s < 4; s++)
                    tv[s] = __ldcg((const float4*)(tl + (long)(ib + s) * INNER + k));
                #pragma unroll
                for (int kk = 0; kk < 4; kk++) {
                    float4 wv = wb4[(j * 4 + kk) * 32];
                    #pragma unroll
                    for (int s = 0; s < 4; s++) fma4(acc[s], fcomp(tv[s], kk), wv);
                }
            }
            #pragma unroll
            for (int s = 0; s < 4; s++) { red4(acc[s], 4); red4(acc[s], 8); red4(acc[s], 16); }

            // per-warp epilogue wait (overlapped behind the GEMM)
            if (lane == 0) {
                const int wX  = 16 * (t2 + 1);
                const int wH  = 16 * t2;
                const int wW1 = 18 * (t2 - 3);
                const int wW2 = 16 * (t2 - 3);
                for (;;) {
                    unsigned h  = *(volatile unsigned*)&cnt2[lvl2];
                    unsigned xp = (lvl2 > 0) ? *(volatile unsigned*)&cnt2[lvl2 - 1] : 0u;
                    unsigned c1 = (lvl2 < 6) ? *(volatile unsigned*)&cnt1[lvl2 + 1] : 0u;
                    unsigned c2 = (lvl2 < 6) ? *(volatile unsigned*)&cnt2[lvl2 + 1] : 0u;
                    if ((int)h >= wH && (lvl2 == 0 || (int)xp >= wX)
                        && (lvl2 == 6 || ((int)c1 >= wW1 && (int)c2 >= wW2))) break;
                }
            }
            __syncwarp();

            if (lane < 4) {
                const int col = cb2 + lane * 4;
                float4 b1v = *(const float4*)&sb1[lane * 4];
                const float* xtp = (lvl2 == 0) ? &g_xe[(long)t2 * BB * HH]
                                               : r_xv[lvl2 - 1][t2 & 3];
                const float* hop = r_xv[lvl2][(t2 + 3) & 3];
                float* hnp = r_xv[lvl2][t2 & 3];
                #pragma unroll
                for (int s = 0; s < 4; s++) {
                    int i = ib + s;
                    float h0 = lrelu(acc[s].x + b1v.x);
                    float h1 = lrelu(acc[s].y + b1v.y);
                    float h2 = lrelu(acc[s].z + b1v.z);
                    float h3 = lrelu(acc[s].w + b1v.w);
                    float bo = sgb[i], xo = sgx[i], ho = sgh[i];
                    float4 xt4 = __ldcg((const float4*)&xtp[i * HH + col]);
                    float4 hl4 = __ldcg((const float4*)&hop[i * HH + col]);
                    float4 hn;
                    hn.x = bo * h0 + xo * xt4.x + ho * hl4.x;
                    hn.y = bo * h1 + xo * xt4.y + ho * hl4.y;
                    hn.z = bo * h2 + xo * xt4.z + ho * hl4.z;
                    hn.w = bo * h3 + xo * xt4.w + ho * hl4.w;
                    *(float4*)&hnp[i * HH + col] = hn;
                    if (lvl2 == LEVELS - 1 && t2 == SS - 1)
                        *(float4*)&out[i * HH + col] = hn;
                }
            }
            __syncthreads();
            if (tid == 0) { __threadfence(); atomicAdd(&cnt2[lvl2], 1u); }
        }
    }
}

extern "C" void kernel_launch(void* const* d_in, const int* in_sizes, int n_in,
                              void* d_out, int out_size) {
    const float* x     = (const float*)d_in[0];
    const float* mask  = (const float*)d_in[1];
    const float* W_emb = (const float*)d_in[3];
    const float* b_emb = (const float*)d_in[4];
    const float* W     = (const float*)d_in[5];
    const float* U     = (const float*)d_in[6];
    const float* b     = (const float*)d_in[7];
    const float* W1    = (const float*)d_in[8];
    const float* b1    = (const float*)d_in[9];
    const float* Wa1   = (const float*)d_in[10];
    const float* Ua1   = (const float*)d_in[11];
    const float* ba1   = (const float*)d_in[12];
    const float* Wa3   = (const float*)d_in[13];
    const float* ba3   = (const float*)d_in[14];
    float* out = (float*)d_out;

    cudaFuncSetAttribute(enc_kernel, cudaFuncAttributeMaxDynamicSharedMemorySize, SMEM_BYTES);
    enc_kernel<<<NB, NT, SMEM_BYTES>>>(x, mask, W_emb, b_emb, W, U, b, W1, b1,
                                       Wa1, Ua1, ba1, Wa3, ba3, out);
}

// round 16
// speedup vs baseline: 1.6302x; 1.6302x over previous
#include <cuda_runtime.h>

#define SS     256
#define BB     64
#define INF    256
#define HH     256
#define INNER  512
#define AA     64
#define LEVELS 7
#define NB     126
#define NT     512
#define NSUPER (SS + 2 * (LEVELS - 1))   // 268

#define OFF_WB1   16384
#define OFF_SG    24576
#define OFF_WA3   24768
#define OFF_B1    24832
#define OFF_BIAS1 24848
#define SMEM_FLOATS 24896
#define SMEM_BYTES  (SMEM_FLOATS * 4)

__device__ float g_xe[SS * BB * HH];
__device__ float g_dm[SS * BB];
__device__ float g_tmpL[LEVELS][BB * INNER];
__device__ float g_aL[LEVELS][BB * AA];
__device__ float r_xv[LEVELS][4][BB * HH];
__device__ float r_nm[LEVELS][4][BB];
__device__ float r_hv[LEVELS][4][BB];

// dataflow counters: cnt1[l] += 1 per phase1-slice (18/t), cnt2[l] += 1 per phase2-slice (16/t)
__device__ unsigned cnt1[LEVELS];
__device__ unsigned cnt2[LEVELS];

__device__ volatile unsigned g_arrive[NB];
__device__ volatile unsigned g_gen = 0;

__device__ __forceinline__ void gbar(unsigned ep) {
    __syncthreads();
    if (blockIdx.x == 0) {
        int tid = threadIdx.x;
        if (tid >= 1 && tid < NB) {
            while (g_arrive[tid] < ep) { }
        }
        __syncthreads();
        if (tid == 0) { __threadfence(); g_gen = ep; }
        __syncthreads();
    } else {
        if (threadIdx.x == 0) {
            __threadfence();
            g_arrive[blockIdx.x] = ep;
            while (g_gen < ep) { }
            __threadfence();
        }
        __syncthreads();
    }
}

__device__ __forceinline__ float lrelu(float z) { return z >= 0.f ? z : 0.01f * z; }

__device__ __forceinline__ void fma4(float4& a, float s, const float4& v) {
    a.x = fmaf(s, v.x, a.x); a.y = fmaf(s, v.y, a.y);
    a.z = fmaf(s, v.z, a.z); a.w = fmaf(s, v.w, a.w);
}
__device__ __forceinline__ float fcomp(const float4& v, int k) {
    return k == 0 ? v.x : k == 1 ? v.y : k == 2 ? v.z : v.w;
}
__device__ __forceinline__ void red4(float4& a, int m) {
    a.x += __shfl_xor_sync(0xffffffffu, a.x, m);
    a.y += __shfl_xor_sync(0xffffffffu, a.y, m);
    a.z += __shfl_xor_sync(0xffffffffu, a.z, m);
    a.w += __shfl_xor_sync(0xffffffffu, a.w, m);
}

// Permuted smem weight layouts (conflict-free; warp reads 512B contiguous per (j,kk))
__device__ __forceinline__ int permP(int k, int cc) {
    int j = k >> 5, kq = (k >> 2) & 7, kk = k & 3;
    int cg = cc >> 4, q = (cc >> 2) & 3, c = cc & 3;
    return ((((j * 4 + kk) * 2 + cg) * 32) + kq * 4 + q) * 4 + c;
}
__device__ __forceinline__ int permB(int k, int cc) {
    int j = k >> 5, kq = (k >> 2) & 7, kk = k & 3;
    int q = cc >> 2, c = cc & 3;
    return (((j * 4 + kk) * 8 + kq) * 4 + q) * 4 + c;
}

// K=256 half, 8 samples via __ldcg (L2-coherent), permuted smem weights.
template<long RS>
__device__ __forceinline__ void gemm8(const float* __restrict__ src0,
                                      const float4* __restrict__ wb4,
                                      int kq, float4 acc[8]) {
    #pragma unroll 2
    for (int j = 0; j < 8; j++) {
        const int k = j * 32 + kq * 4;
        float4 av[8];
        #pragma unroll
        for (int s = 0; s < 8; s++)
            av[s] = __ldcg((const float4*)(src0 + (long)s * RS + k));
        #pragma unroll
        for (int kk = 0; kk < 4; kk++) {
            float4 wv = wb4[(j * 4 + kk) * 64];
            #pragma unroll
            for (int s = 0; s < 8; s++) fma4(acc[s], fcomp(av[s], kk), wv);
        }
    }
}

__global__ void __launch_bounds__(NT, 1)
enc_kernel(const float* __restrict__ x, const float* __restrict__ mask,
           const float* __restrict__ W_emb, const float* __restrict__ b_emb,
           const float* __restrict__ W, const float* __restrict__ U, const float* __restrict__ b,
           const float* __restrict__ W1, const float* __restrict__ b1,
           const float* __restrict__ Wa1, const float* __restrict__ Ua1, const float* __restrict__ ba1,
           const float* __restrict__ Wa3, const float* __restrict__ ba3,
           float* __restrict__ out)
{
    extern __shared__ float smem[];
    float* const wP     = smem;                  // [512][32] permuted
    float* const wB1    = smem + OFF_WB1;        // [512][16] permuted
    float* const sgb    = smem + OFF_SG;
    float* const sgx    = smem + OFF_SG + 64;
    float* const sgh    = smem + OFF_SG + 128;
    float* const swa3   = smem + OFF_WA3;
    float* const sb1    = smem + OFF_B1;
    float* const sbias1 = smem + OFF_BIAS1;

    const int tid = threadIdx.x, bid = blockIdx.x;
    const int w = tid >> 5, lane = tid & 31;
    const int kq = lane >> 2, q = lane & 3;
    unsigned ep = g_gen;

    const int lvl1 = bid / 18, cb1 = (bid % 18) * 32;
    const bool p2on = bid < 112;
    const int lvl2 = bid >> 4, cb2 = (bid & 15) * 16;

    const int sg1 = w & 7, cg1 = w >> 3;
    const int ib1 = sg1 * 8;

    // ---- init dm + ring zero + counters ----
    for (int idx = bid * NT + tid; idx < SS * BB; idx += NB * NT) {
        int t = idx >> 6, i = idx & 63;
        g_dm[idx] = mask[i * SS + t];
    }
    for (int idx = bid * NT + tid; idx < LEVELS * BB * HH; idx += NB * NT)
        r_xv[idx >> 14][3][idx & 16383] = 0.f;
    for (int idx = bid * NT + tid; idx < LEVELS * BB; idx += NB * NT)
        r_hv[idx >> 6][3][idx & 63] = 0.f;
    if (bid == NB - 1 && tid < LEVELS) { cnt1[tid] = 0; cnt2[tid] = 0; }

    // ---- embedding (120 blocks: 8 col-slices x 15 t-groups) ----
    if (bid < 120) {
        const int esl = bid & 7, egr = bid >> 3;
        for (int idx = tid; idx < 256 * 32; idx += NT) {
            int k = idx >> 5, cc = idx & 31;
            wP[permP(k, cc)] = W_emb[k * HH + esl * 32 + cc];
        }
        __syncthreads();
        const float4* wb4 = (const float4*)wP + cg1 * 32 + kq * 4 + q;
        for (int n = egr; n < SS; n += 15) {
            float4 acc[8];
            #pragma unroll
            for (int s = 0; s < 8; s++) acc[s] = make_float4(0.f, 0.f, 0.f, 0.f);
            gemm8<(long)SS * INF>(x + ((long)ib1 * SS + n) * INF, wb4, kq, acc);
            #pragma unroll
            for (int s = 0; s < 8; s++) { red4(acc[s], 4); red4(acc[s], 8); red4(acc[s], 16); }
            if (lane < 4) {
                int col = esl * 32 + cg1 * 16 + lane * 4;
                float4 be = __ldg((const float4*)&b_emb[col]);
                #pragma unroll
                for (int s = 0; s < 8; s++) {
                    float4 o = acc[s];
                    o.x += be.x; o.y += be.y; o.z += be.z; o.w += be.w;
                    *(float4*)&g_xe[((long)n * BB + ib1 + s) * HH + col] = o;
                }
            }
        }
        __syncthreads();
    }

    // ---- stage persistent weights (permuted) ----
    for (int idx = tid; idx < 512 * 32; idx += NT) {
        int k = idx >> 5, cc = idx & 31, col = cb1 + cc;
        float v;
        if (col < 512) v = (k < 256) ? W[k * INNER + col] : U[(k - 256) * INNER + col];
        else { int a = col - 512; v = (k < 256) ? Wa1[k * AA + a] : Ua1[(k - 256) * AA + a]; }
        wP[permP(k & 255, cc) + (k >> 8) * 8192] = v;
    }
    if (p2on) {
        for (int idx = tid; idx < 512 * 16; idx += NT) {
            int k = idx >> 4, cc = idx & 15;
            wB1[permB(k, cc)] = W1[k * HH + cb2 + cc];
        }
        if (tid < 16) sb1[tid] = b1[cb2 + tid];
    }
    if (tid < 64) swa3[tid] = Wa3[tid];
    if (tid < 32) {
        int col = cb1 + tid;
        sbias1[tid] = (col < 512) ? b[col] : ba1[col - 512];
    }
    const float ba3v = __ldg(ba3);
    gbar(++ep);

    // ---- wavefront supersteps (dataflow-synced; no global barrier) ----
    for (int u = 0; u < NSUPER; u++) {
        // ======== phase 1: [tmp|a] = lrelu([xt|h] @ [W;U|Wa1;Ua1] + bias) ========
        const int t1 = u - 2 * lvl1;
        if ((unsigned)t1 < SS) {
            if (tid == 0) {
                const int w1 = 16 * t1, w2 = 16 * (t1 + 1);
                for (;;) {
                    unsigned a = *(volatile unsigned*)&cnt2[lvl1];
                    unsigned bv = (lvl1 > 0) ? *(volatile unsigned*)&cnt2[lvl1 - 1] : 0u;
                    if ((int)a >= w1 && (lvl1 == 0 || (int)bv >= w2)) break;
                }
            }
            __syncthreads();

            const float* xt = (lvl1 == 0) ? &g_xe[(long)t1 * BB * HH]
                                          : r_xv[lvl1 - 1][t1 & 3];
            const float* hp = r_xv[lvl1][(t1 + 3) & 3];
            const float4* wb4 = (const float4*)wP + cg1 * 32 + kq * 4 + q;
            float4 acc[8];
            #pragma unroll
            for (int s = 0; s < 8; s++) acc[s] = make_float4(0.f, 0.f, 0.f, 0.f);
            gemm8<HH>(xt + (long)ib1 * HH, wb4,        kq, acc);
            gemm8<HH>(hp + (long)ib1 * HH, wb4 + 2048, kq, acc);
            #pragma unroll
            for (int s = 0; s < 8; s++) { red4(acc[s], 4); red4(acc[s], 8); red4(acc[s], 16); }
            if (lane < 4) {
                const int col = cb1 + cg1 * 16 + lane * 4;
                float4 bv = *(const float4*)&sbias1[cg1 * 16 + lane * 4];
                #pragma unroll
                for (int s = 0; s < 8; s++) {
                    int i = ib1 + s;
                    float4 o;
                    o.x = lrelu(acc[s].x + bv.x); o.y = lrelu(acc[s].y + bv.y);
                    o.z = lrelu(acc[s].z + bv.z); o.w = lrelu(acc[s].w + bv.w);
                    if (col < 512) *(float4*)&g_tmpL[lvl1][i * INNER + col] = o;
                    else           *(float4*)&g_aL[lvl1][i * AA + col - 512] = o;
                }
            }
            __syncthreads();
            if (tid == 0) { __threadfence(); atomicAdd(&cnt1[lvl1], 1u); }
        }

        // ======== phase 2: gates + h = g(lrelu(tmp @ W1 + b1), xt, h_old) ========
        const int t2 = u - 2 * lvl2;
        if (p2on && (unsigned)t2 < SS) {
            if (tid == 0) {
                const int wA = 18 * (t2 + 1);
                const int wB = 16 * ((t2 + 2 > 256) ? 256 : (t2 + 2));
                const int wC = 18 * (t2 - 3);
                const int wD = 16 * (t2 - 3);
                for (;;) {
                    unsigned a = *(volatile unsigned*)&cnt1[lvl2];
                    unsigned bv = (lvl2 > 0) ? *(volatile unsigned*)&cnt2[lvl2 - 1] : 0u;
                    unsigned c = (lvl2 < 6) ? *(volatile unsigned*)&cnt1[lvl2 + 1] : 0u;
                    unsigned d = (lvl2 < 6) ? *(volatile unsigned*)&cnt2[lvl2 + 1] : 0u;
                    bool ok = ((int)a >= wA)
                           && (lvl2 == 0 || (int)bv >= wB)
                           && (lvl2 == 6 || ((int)c >= wC && (int)d >= wD));
                    if (ok) break;
                }
            }
            __syncthreads();

            {   // gate scalars: warp-local (warp w handles samples 4w..4w+3)
                int i = tid >> 3, qtr = tid & 7;
                const float* ar = &g_aL[lvl2][i * AA + qtr * 8];
                float p = 0.f;
                #pragma unroll
                for (int c = 0; c < 8; c += 4) {
                    float4 a4 = __ldcg((const float4*)&ar[c]);
                    float4 w4 = *(const float4*)&swa3[qtr * 8 + c];
                    p += a4.x * w4.x + a4.y * w4.y + a4.z * w4.z + a4.w * w4.w;
                }
                p += __shfl_xor_sync(0xffffffffu, p, 1);
                p += __shfl_xor_sync(0xffffffffu, p, 2);
                p += __shfl_xor_sync(0xffffffffu, p, 4);
                if (qtr == 0) {
                    float sg  = 0.2f * (p + ba3v) + 0.5f;
                    float nmr = fminf(fmaxf(sg, 0.f), 1.f);
                    float lv  = (t2 == SS - 1) ? 1.f : 0.f;
                    float pm, ph;
                    if (lvl2 == 0) { pm = g_dm[t2 * BB + i]; ph = pm; }
                    else {
                        pm = (t2 == SS - 1) ? 1.f : __ldcg(&r_nm[lvl2 - 1][(t2 + 1) & 3][i]);
                        ph = __ldcg(&r_hv[lvl2 - 1][t2 & 3][i]);
                    }
                    float hvp = __ldcg(&r_hv[lvl2][(t2 + 3) & 3][i]);
                    float nm   = (1.f - lv) * (pm * ph * nmr);
                    float both = pm * ph * (1.f - nm) * hvp;
                    float xo   = pm * ph * (nm + (1.f - nm) * (1.f - hvp));
                    float ho   = (1.f - pm + pm * (1.f - ph)) * (1.f - nm) * hvp;
                    sgb[i] = both; sgx[i] = xo; sgh[i] = ho;
                    r_nm[lvl2][t2 & 3][i] = nm;
                    r_hv[lvl2][t2 & 3][i] = both + xo + ho;
                }
            }
            __syncwarp();                       // gates are warp-local: no block barrier

            // B GEMM: K=512, 16 cols; warp = 4 samples x 16 cols, permuted weights
            const float* tl = g_tmpL[lvl2];
            const int ib = 4 * w;
            const float4* wb4 = (const float4*)wB1 + kq * 4 + q;
            float4 acc[4];
            #pragma unroll
            for (int s = 0; s < 4; s++) acc[s] = make_float4(0.f, 0.f, 0.f, 0.f);
            #pragma unroll 2
            for (int j = 0; j < 16; j++) {
                const int k = j * 32 + kq * 4;
                float4 tv[4];
                #pragma unroll
                for (int s = 0; s < 4; s++)
                    tv[s] = __ldcg((const float4*)(tl + (long)(ib + s) * INNER + k));
                #pragma unroll
                for (int kk = 0; kk < 4; kk++) {
                    float4 wv = wb4[(j * 4 + kk) * 32];
                    #pragma unroll
                    for (int s = 0; s < 4; s++) fma4(acc[s], fcomp(tv[s], kk), wv);
                }
            }
            #pragma unroll
            for (int s = 0; s < 4; s++) { red4(acc[s], 4); red4(acc[s], 8); red4(acc[s], 16); }
            if (lane < 4) {
                const int col = cb2 + lane * 4;
                float4 b1v = *(const float4*)&sb1[lane * 4];
                const float* xtp = (lvl2 == 0) ? &g_xe[(long)t2 * BB * HH]
                                               : r_xv[lvl2 - 1][t2 & 3];
                const float* hop = r_xv[lvl2][(t2 + 3) & 3];
                float* hnp = r_xv[lvl2][t2 & 3];
                #pragma unroll
                for (int s = 0; s < 4; s++) {
                    int i = ib + s;
                    float h0 = lrelu(acc[s].x + b1v.x);
                    float h1 = lrelu(acc[s].y + b1v.y);
                    float h2 = lrelu(acc[s].z + b1v.z);
                    float h3 = lrelu(acc[s].w + b1v.w);
                    float bo = sgb[i], xo = sgx[i], ho = sgh[i];
                    float4 xt4 = __ldcg((const float4*)&xtp[i * HH + col]);
                    float4 hl4 = __ldcg((const float4*)&hop[i * HH + col]);
                    float4 hn;
                    hn.x = bo * h0 + xo * xt4.x + ho * hl4.x;
                    hn.y = bo * h1 + xo * xt4.y + ho * hl4.y;
                    hn.z = bo * h2 + xo * xt4.z + ho * hl4.z;
                    hn.w = bo * h3 + xo * xt4.w + ho * hl4.w;
                    *(float4*)&hnp[i * HH + col] = hn;
                    if (lvl2 == LEVELS - 1 && t2 == SS - 1)
                        *(float4*)&out[i * HH + col] = hn;
                }
            }
            __syncthreads();
            if (tid == 0) { __threadfence(); atomicAdd(&cnt2[lvl2], 1u); }
        }
    }
}

extern "C" void kernel_launch(void* const* d_in, const int* in_sizes, int n_in,
                              void* d_out, int out_size) {
    const float* x     = (const float*)d_in[0];
    const float* mask  = (const float*)d_in[1];
    const float* W_emb = (const float*)d_in[3];
    const float* b_emb = (const float*)d_in[4];
    const float* W     = (const float*)d_in[5];
    const float* U     = (const float*)d_in[6];
    const float* b     = (const float*)d_in[7];
    const float* W1    = (const float*)d_in[8];
    const float* b1    = (const float*)d_in[9];
    const float* Wa1   = (const float*)d_in[10];
    const float* Ua1   = (const float*)d_in[11];
    const float* ba1   = (const float*)d_in[12];
    const float* Wa3   = (const float*)d_in[13];
    const float* ba3   = (const float*)d_in[14];
    float* out = (float*)d_out;

    cudaFuncSetAttribute(enc_kernel, cudaFuncAttributeMaxDynamicSharedMemorySize, SMEM_BYTES);
    enc_kernel<<<NB, NT, SMEM_BYTES>>>(x, mask, W_emb, b_emb, W, U, b, W1, b1,
                                       Wa1, Ua1, ba1, Wa3, ba3, out);
}

// round 17
// speedup vs baseline: 1.6448x; 1.0089x over previous
#include <cuda_runtime.h>

#define SS     256
#define BB     64
#define INF    256
#define HH     256
#define INNER  512
#define AA     64
#define LEVELS 7
#define NB     126
#define NT     512
#define NSUPER (SS + 2 * (LEVELS - 1))   // 268

#define OFF_WB1   16384
#define OFF_SG    24576
#define OFF_WA3   24768
#define OFF_B1    24832
#define OFF_BIAS1 24848
#define SMEM_FLOATS 24896
#define SMEM_BYTES  (SMEM_FLOATS * 4)

__device__ float g_xe[SS * BB * HH];
__device__ float g_dm[SS * BB];
__device__ float g_tmpL[LEVELS][BB * INNER];
__device__ float g_aL[LEVELS][BB * AA];
__device__ float r_xv[LEVELS][4][BB * HH];
__device__ float r_nm[LEVELS][4][BB];
__device__ float r_hv[LEVELS][4][BB];

// dataflow counters: cnt1[l] += 1 per phase1-slice (18/t), cnt2[l] += 1 per phase2-slice (16/t)
__device__ unsigned cnt1[LEVELS];
__device__ unsigned cnt2[LEVELS];

__device__ volatile unsigned g_arrive[NB];
__device__ volatile unsigned g_gen = 0;

__device__ __forceinline__ void gbar(unsigned ep) {
    __syncthreads();
    if (blockIdx.x == 0) {
        int tid = threadIdx.x;
        if (tid >= 1 && tid < NB) {
            while (g_arrive[tid] < ep) { }
        }
        __syncthreads();
        if (tid == 0) { __threadfence(); g_gen = ep; }
        __syncthreads();
    } else {
        if (threadIdx.x == 0) {
            __threadfence();
            g_arrive[blockIdx.x] = ep;
            while (g_gen < ep) { }
            __threadfence();
        }
        __syncthreads();
    }
}

__device__ __forceinline__ float lrelu(float z) { return z >= 0.f ? z : 0.01f * z; }

__device__ __forceinline__ void fma4(float4& a, float s, const float4& v) {
    a.x = fmaf(s, v.x, a.x); a.y = fmaf(s, v.y, a.y);
    a.z = fmaf(s, v.z, a.z); a.w = fmaf(s, v.w, a.w);
}
__device__ __forceinline__ float fcomp(const float4& v, int k) {
    return k == 0 ? v.x : k == 1 ? v.y : k == 2 ? v.z : v.w;
}
__device__ __forceinline__ void red4(float4& a, int m) {
    a.x += __shfl_xor_sync(0xffffffffu, a.x, m);
    a.y += __shfl_xor_sync(0xffffffffu, a.y, m);
    a.z += __shfl_xor_sync(0xffffffffu, a.z, m);
    a.w += __shfl_xor_sync(0xffffffffu, a.w, m);
}

// Permuted smem weight layouts (conflict-free; warp reads 512B contiguous per (j,kk))
__device__ __forceinline__ int permP(int k, int cc) {
    int j = k >> 5, kq = (k >> 2) & 7, kk = k & 3;
    int cg = cc >> 4, q = (cc >> 2) & 3, c = cc & 3;
    return ((((j * 4 + kk) * 2 + cg) * 32) + kq * 4 + q) * 4 + c;
}
__device__ __forceinline__ int permB(int k, int cc) {
    int j = k >> 5, kq = (k >> 2) & 7, kk = k & 3;
    int q = cc >> 2, c = cc & 3;
    return (((j * 4 + kk) * 8 + kq) * 4 + q) * 4 + c;
}

// K=256 half, 8 samples via __ldcg, permuted smem weights.
template<long RS>
__device__ __forceinline__ void gemm8(const float* __restrict__ src0,
                                      const float4* __restrict__ wb4,
                                      int kq, float4 acc[8]) {
    #pragma unroll 2
    for (int j = 0; j < 8; j++) {
        const int k = j * 32 + kq * 4;
        float4 av[8];
        #pragma unroll
        for (int s = 0; s < 8; s++)
            av[s] = __ldcg((const float4*)(src0 + (long)s * RS + k));
        #pragma unroll
        for (int kk = 0; kk < 4; kk++) {
            float4 wv = wb4[(j * 4 + kk) * 64];
            #pragma unroll
            for (int s = 0; s < 8; s++) fma4(acc[s], fcomp(av[s], kk), wv);
        }
    }
}

__global__ void __launch_bounds__(NT, 1)
enc_kernel(const float* __restrict__ x, const float* __restrict__ mask,
           const float* __restrict__ W_emb, const float* __restrict__ b_emb,
           const float* __restrict__ W, const float* __restrict__ U, const float* __restrict__ b,
           const float* __restrict__ W1, const float* __restrict__ b1,
           const float* __restrict__ Wa1, const float* __restrict__ Ua1, const float* __restrict__ ba1,
           const float* __restrict__ Wa3, const float* __restrict__ ba3,
           float* __restrict__ out)
{
    extern __shared__ float smem[];
    float* const wP     = smem;                  // [512][32] permuted
    float* const wB1    = smem + OFF_WB1;        // [512][16] permuted
    float* const sgb    = smem + OFF_SG;
    float* const sgx    = smem + OFF_SG + 64;
    float* const sgh    = smem + OFF_SG + 128;
    float* const swa3   = smem + OFF_WA3;
    float* const sb1    = smem + OFF_B1;
    float* const sbias1 = smem + OFF_BIAS1;

    const int tid = threadIdx.x, bid = blockIdx.x;
    const int w = tid >> 5, lane = tid & 31;
    const int kq = lane >> 2, q = lane & 3;
    unsigned ep = g_gen;

    const int lvl1 = bid / 18, cb1 = (bid % 18) * 32;
    const bool p2on = bid < 112;
    const int lvl2 = bid >> 4, cb2 = (bid & 15) * 16;

    const int sg1 = w & 7, cg1 = w >> 3;
    const int ib1 = sg1 * 8;

    // ---- init dm + ring zero + counters ----
    for (int idx = bid * NT + tid; idx < SS * BB; idx += NB * NT) {
        int t = idx >> 6, i = idx & 63;
        g_dm[idx] = mask[i * SS + t];
    }
    for (int idx = bid * NT + tid; idx < LEVELS * BB * HH; idx += NB * NT)
        r_xv[idx >> 14][3][idx & 16383] = 0.f;
    for (int idx = bid * NT + tid; idx < LEVELS * BB; idx += NB * NT)
        r_hv[idx >> 6][3][idx & 63] = 0.f;
    if (bid == NB - 1 && tid < LEVELS) { cnt1[tid] = 0; cnt2[tid] = 0; }

    // ---- embedding (120 blocks: 8 col-slices x 15 t-groups) ----
    if (bid < 120) {
        const int esl = bid & 7, egr = bid >> 3;
        for (int idx = tid; idx < 256 * 32; idx += NT) {
            int k = idx >> 5, cc = idx & 31;
            wP[permP(k, cc)] = W_emb[k * HH + esl * 32 + cc];
        }
        __syncthreads();
        const float4* wb4 = (const float4*)wP + cg1 * 32 + kq * 4 + q;
        for (int n = egr; n < SS; n += 15) {
            float4 acc[8];
            #pragma unroll
            for (int s = 0; s < 8; s++) acc[s] = make_float4(0.f, 0.f, 0.f, 0.f);
            gemm8<(long)SS * INF>(x + ((long)ib1 * SS + n) * INF, wb4, kq, acc);
            #pragma unroll
            for (int s = 0; s < 8; s++) { red4(acc[s], 4); red4(acc[s], 8); red4(acc[s], 16); }
            if (lane < 4) {
                int col = esl * 32 + cg1 * 16 + lane * 4;
                float4 be = __ldg((const float4*)&b_emb[col]);
                #pragma unroll
                for (int s = 0; s < 8; s++) {
                    float4 o = acc[s];
                    o.x += be.x; o.y += be.y; o.z += be.z; o.w += be.w;
                    *(float4*)&g_xe[((long)n * BB + ib1 + s) * HH + col] = o;
                }
            }
        }
        __syncthreads();
    }

    // ---- stage persistent weights (permuted) ----
    for (int idx = tid; idx < 512 * 32; idx += NT) {
        int k = idx >> 5, cc = idx & 31, col = cb1 + cc;
        float v;
        if (col < 512) v = (k < 256) ? W[k * INNER + col] : U[(k - 256) * INNER + col];
        else { int a = col - 512; v = (k < 256) ? Wa1[k * AA + a] : Ua1[(k - 256) * AA + a]; }
        wP[permP(k & 255, cc) + (k >> 8) * 8192] = v;
    }
    if (p2on) {
        for (int idx = tid; idx < 512 * 16; idx += NT) {
            int k = idx >> 4, cc = idx & 15;
            wB1[permB(k, cc)] = W1[k * HH + cb2 + cc];
        }
        if (tid < 16) sb1[tid] = b1[cb2 + tid];
    }
    if (tid < 64) swa3[tid] = Wa3[tid];
    if (tid < 32) {
        int col = cb1 + tid;
        sbias1[tid] = (col < 512) ? b[col] : ba1[col - 512];
    }
    const float ba3v = __ldg(ba3);
    gbar(++ep);

    // ---- wavefront supersteps (dataflow-synced, deferred waits) ----
    for (int u = 0; u < NSUPER; u++) {
        // ======== phase 1: [tmp|a] = lrelu([xt|h] @ [W;U|Wa1;Ua1] + bias) ========
        const int t1 = u - 2 * lvl1;
        if ((unsigned)t1 < SS) {
            // wait #1: xt only (h(lvl1-1, t1), finished 2 supersteps ago)
            if (lvl1 > 0) {
                if (tid == 0) {
                    const int w2 = 16 * (t1 + 1);
                    while ((int)(*(volatile unsigned*)&cnt2[lvl1 - 1]) < w2) { }
                }
                __syncthreads();
            }
            const float* xt = (lvl1 == 0) ? &g_xe[(long)t1 * BB * HH]
                                          : r_xv[lvl1 - 1][t1 & 3];
            const float4* wb4 = (const float4*)wP + cg1 * 32 + kq * 4 + q;
            float4 acc[8];
            #pragma unroll
            for (int s = 0; s < 8; s++) acc[s] = make_float4(0.f, 0.f, 0.f, 0.f);
            gemm8<HH>(xt + (long)ib1 * HH, wb4, kq, acc);

            // wait #2: hp (fresh, 1 superstep ago) + tmp/aL WAR — hidden behind xt GEMM
            if (tid == 0) {
                const int w1 = 16 * t1;
                while ((int)(*(volatile unsigned*)&cnt2[lvl1]) < w1) { }
            }
            __syncthreads();
            const float* hp = r_xv[lvl1][(t1 + 3) & 3];
            gemm8<HH>(hp + (long)ib1 * HH, wb4 + 2048, kq, acc);
            #pragma unroll
            for (int s = 0; s < 8; s++) { red4(acc[s], 4); red4(acc[s], 8); red4(acc[s], 16); }
            if (lane < 4) {
                const int col = cb1 + cg1 * 16 + lane * 4;
                float4 bv = *(const float4*)&sbias1[cg1 * 16 + lane * 4];
                #pragma unroll
                for (int s = 0; s < 8; s++) {
                    int i = ib1 + s;
                    float4 o;
                    o.x = lrelu(acc[s].x + bv.x); o.y = lrelu(acc[s].y + bv.y);
                    o.z = lrelu(acc[s].z + bv.z); o.w = lrelu(acc[s].w + bv.w);
                    if (col < 512) *(float4*)&g_tmpL[lvl1][i * INNER + col] = o;
                    else           *(float4*)&g_aL[lvl1][i * AA + col - 512] = o;
                }
            }
            __syncthreads();
            if (tid == 0) { __threadfence(); atomicAdd(&cnt1[lvl1], 1u); }
        }

        // ======== phase 2: B GEMM first, gates+epilogue after deferred wait ========
        const int t2 = u - 2 * lvl2;
        if (p2on && (unsigned)t2 < SS) {
            // wait #1: tmp/aL of (lvl2,t2) — the only same-superstep dependency
            if (tid == 0) {
                const int wA = 18 * (t2 + 1);
                while ((int)(*(volatile unsigned*)&cnt1[lvl2]) < wA) { }
            }
            __syncthreads();

            // B GEMM: K=512, 16 cols; warp = 4 samples x 16 cols, permuted weights
            const float* tl = g_tmpL[lvl2];
            const int ib = 4 * w;
            const float4* wb4 = (const float4*)wB1 + kq * 4 + q;
            float4 acc[4];
            #pragma unroll
            for (int s = 0; s < 4; s++) acc[s] = make_float4(0.f, 0.f, 0.f, 0.f);
            #pragma unroll 2
            for (int j = 0; j < 16; j++) {
                const int k = j * 32 + kq * 4;
                float4 tv[4];
                #pragma unroll
                for (int s = 0; s < 4; s++)
                    tv[s] = __ldcg((const float4*)(tl + (long)(ib + s) * INNER + k));
                #pragma unroll
                for (int kk = 0; kk < 4; kk++) {
                    float4 wv = wb4[(j * 4 + kk) * 32];
                    #pragma unroll
                    for (int s = 0; s < 4; s++) fma4(acc[s], fcomp(tv[s], kk), wv);
                }
            }
            #pragma unroll
            for (int s = 0; s < 4; s++) { red4(acc[s], 4); red4(acc[s], 8); red4(acc[s], 16); }

            // wait #2: gate deps (prev superstep) + ring-WAR (old) — hidden behind GEMM
            if (tid == 0) {
                const int wB = 16 * ((t2 + 2 > 256) ? 256 : (t2 + 2));
                const int wC = 18 * (t2 - 3);
                const int wD = 16 * (t2 - 3);
                for (;;) {
                    unsigned bv = (lvl2 > 0) ? *(volatile unsigned*)&cnt2[lvl2 - 1] : 0u;
                    unsigned c = (lvl2 < 6) ? *(volatile unsigned*)&cnt1[lvl2 + 1] : 0u;
                    unsigned d = (lvl2 < 6) ? *(volatile unsigned*)&cnt2[lvl2 + 1] : 0u;
                    bool ok = (lvl2 == 0 || (int)bv >= wB)
                           && (lvl2 == 6 || ((int)c >= wC && (int)d >= wD));
                    if (ok) break;
                }
            }
            __syncthreads();

            {   // gate scalars: warp-local (warp w handles samples 4w..4w+3)
                int i = tid >> 3, qtr = tid & 7;
                const float* ar = &g_aL[lvl2][i * AA + qtr * 8];
                float p = 0.f;
                #pragma unroll
                for (int c = 0; c < 8; c += 4) {
                    float4 a4 = __ldcg((const float4*)&ar[c]);
                    float4 w4 = *(const float4*)&swa3[qtr * 8 + c];
                    p += a4.x * w4.x + a4.y * w4.y + a4.z * w4.z + a4.w * w4.w;
                }
                p += __shfl_xor_sync(0xffffffffu, p, 1);
                p += __shfl_xor_sync(0xffffffffu, p, 2);
                p += __shfl_xor_sync(0xffffffffu, p, 4);
                if (qtr == 0) {
                    float sg  = 0.2f * (p + ba3v) + 0.5f;
                    float nmr = fminf(fmaxf(sg, 0.f), 1.f);
                    float lv  = (t2 == SS - 1) ? 1.f : 0.f;
                    float pm, ph;
                    if (lvl2 == 0) { pm = g_dm[t2 * BB + i]; ph = pm; }
                    else {
                        pm = (t2 == SS - 1) ? 1.f : __ldcg(&r_nm[lvl2 - 1][(t2 + 1) & 3][i]);
                        ph = __ldcg(&r_hv[lvl2 - 1][t2 & 3][i]);
                    }
                    float hvp = __ldcg(&r_hv[lvl2][(t2 + 3) & 3][i]);
                    float nm   = (1.f - lv) * (pm * ph * nmr);
                    float both = pm * ph * (1.f - nm) * hvp;
                    float xo   = pm * ph * (nm + (1.f - nm) * (1.f - hvp));
                    float ho   = (1.f - pm + pm * (1.f - ph)) * (1.f - nm) * hvp;
                    sgb[i] = both; sgx[i] = xo; sgh[i] = ho;
                    r_nm[lvl2][t2 & 3][i] = nm;
                    r_hv[lvl2][t2 & 3][i] = both + xo + ho;
                }
            }
            __syncwarp();                       // gates are warp-local

            if (lane < 4) {
                const int col = cb2 + lane * 4;
                float4 b1v = *(const float4*)&sb1[lane * 4];
                const float* xtp = (lvl2 == 0) ? &g_xe[(long)t2 * BB * HH]
                                               : r_xv[lvl2 - 1][t2 & 3];
                const float* hop = r_xv[lvl2][(t2 + 3) & 3];
                float* hnp = r_xv[lvl2][t2 & 3];
                #pragma unroll
                for (int s = 0; s < 4; s++) {
                    int i = ib + s;
                    float h0 = lrelu(acc[s].x + b1v.x);
                    float h1 = lrelu(acc[s].y + b1v.y);
                    float h2 = lrelu(acc[s].z + b1v.z);
                    float h3 = lrelu(acc[s].w + b1v.w);
                    float bo = sgb[i], xo = sgx[i], ho = sgh[i];
                    float4 xt4 = __ldcg((const float4*)&xtp[i * HH + col]);
                    float4 hl4 = __ldcg((const float4*)&hop[i * HH + col]);
                    float4 hn;
                    hn.x = bo * h0 + xo * xt4.x + ho * hl4.x;
                    hn.y = bo * h1 + xo * xt4.y + ho * hl4.y;
                    hn.z = bo * h2 + xo * xt4.z + ho * hl4.z;
                    hn.w = bo * h3 + xo * xt4.w + ho * hl4.w;
                    *(float4*)&hnp[i * HH + col] = hn;
                    if (lvl2 == LEVELS - 1 && t2 == SS - 1)
                        *(float4*)&out[i * HH + col] = hn;
                }
            }
            __syncthreads();
            if (tid == 0) { __threadfence(); atomicAdd(&cnt2[lvl2], 1u); }
        }
    }
}

extern "C" void kernel_launch(void* const* d_in, const int* in_sizes, int n_in,
                              void* d_out, int out_size) {
    const float* x     = (const float*)d_in[0];
    const float* mask  = (const float*)d_in[1];
    const float* W_emb = (const float*)d_in[3];
    const float* b_emb = (const float*)d_in[4];
    const float* W     = (const float*)d_in[5];
    const float* U     = (const float*)d_in[6];
    const float* b     = (const float*)d_in[7];
    const float* W1    = (const float*)d_in[8];
    const float* b1    = (const float*)d_in[9];
    const float* Wa1   = (const float*)d_in[10];
    const float* Ua1   = (const float*)d_in[11];
    const float* ba1   = (const float*)d_in[12];
    const float* Wa3   = (const float*)d_in[13];
    const float* ba3   = (const float*)d_in[14];
    float* out = (float*)d_out;

    cudaFuncSetAttribute(enc_kernel, cudaFuncAttributeMaxDynamicSharedMemorySize, SMEM_BYTES);
    enc_kernel<<<NB, NT, SMEM_BYTES>>>(x, mask, W_emb, b_emb, W, U, b, W1, b1,
                                       Wa1, Ua1, ba1, Wa3, ba3, out);
}